// round 16
// baseline (speedup 1.0000x reference)
#include <cuda_runtime.h>
#include <cuda_fp16.h>
#include <math.h>
#include <stdint.h>

#define EPSF 1e-6f
#define NTOK 4096
#define DDIM 1024
#define HDIM 64
#define MDIM 2736
#define SEQ  1024
#define KPADM 2752
#define NPADM 2816

typedef __half fp16;

// ---------------- scratch ----------------
__device__ float g_x1[NTOK * DDIM];
__device__ fp16 g_gateh[NTOK * KPADM];

__device__ fp16 g_ai[NTOK * DDIM];
__device__ fp16 g_q[NTOK * DDIM];
__device__ fp16 g_k[NTOK * DDIM];
__device__ fp16 g_v[NTOK * DDIM];
__device__ fp16 g_aop[NTOK * DDIM];
__device__ fp16 g_mi[NTOK * DDIM];
__device__ fp16 g_hb[NTOK * KPADM];

__device__ fp16 g_wqT[DDIM * DDIM];
__device__ fp16 g_wkT[DDIM * DDIM];
__device__ fp16 g_wvT[DDIM * DDIM];
__device__ fp16 g_woT[DDIM * DDIM];
__device__ fp16 g_wgT[NPADM * DDIM];
__device__ fp16 g_wuT[NPADM * DDIM];
__device__ fp16 g_wdT[DDIM * KPADM];

__device__ float g_u[7][MDIM];
__device__ float g_w[7][MDIM];
__device__ float g_n2[7][16];
__device__ float g_sigma[7];

__constant__ int c_rows[7] = {1024, 1024, 1024, 1024, 1024, 1024, 2736};
__constant__ int c_cols[7] = {1024, 1024, 1024, 1024, 2736, 2736, 1024};
__constant__ int c_nct[7]  = {4, 4, 4, 4, 11, 11, 4};
__constant__ int c_nrc[7]  = {32, 32, 32, 32, 32, 32, 86};
#define BWD_CH 32

struct WP { const float* p[7]; };

// ---------------- PTX helpers ----------------
__device__ __forceinline__ uint32_t s2u(const void* p) {
    uint32_t a;
    asm("{ .reg .u64 t; cvta.to.shared.u64 t, %1; cvt.u32.u64 %0, t; }" : "=r"(a) : "l"(p));
    return a;
}
__device__ __forceinline__ void cpa16(uint32_t d, const void* g) {
    asm volatile("cp.async.cg.shared.global [%0], [%1], 16;" :: "r"(d), "l"(g) : "memory");
}
__device__ __forceinline__ void cpa_commit() { asm volatile("cp.async.commit_group;" ::: "memory"); }
template <int N> __device__ __forceinline__ void cpa_wait() {
    asm volatile("cp.async.wait_group %0;" :: "n"(N) : "memory");
}
__device__ __forceinline__ void ldmx4(uint32_t* r, uint32_t a) {
    asm volatile("ldmatrix.sync.aligned.m8n8.x4.shared.b16 {%0,%1,%2,%3}, [%4];"
                 : "=r"(r[0]), "=r"(r[1]), "=r"(r[2]), "=r"(r[3]) : "r"(a));
}
__device__ __forceinline__ void ldmx4t(uint32_t* r, uint32_t a) {
    asm volatile("ldmatrix.sync.aligned.m8n8.x4.trans.shared.b16 {%0,%1,%2,%3}, [%4];"
                 : "=r"(r[0]), "=r"(r[1]), "=r"(r[2]), "=r"(r[3]) : "r"(a));
}
__device__ __forceinline__ void mma16816(float* c, const uint32_t* a, const uint32_t* b) {
    asm volatile(
        "mma.sync.aligned.m16n8k16.row.col.f32.f16.f16.f32 "
        "{%0,%1,%2,%3}, {%4,%5,%6,%7}, {%8,%9}, {%0,%1,%2,%3};"
        : "+f"(c[0]), "+f"(c[1]), "+f"(c[2]), "+f"(c[3])
        : "r"(a[0]), "r"(a[1]), "r"(a[2]), "r"(a[3]), "r"(b[0]), "r"(b[1]));
}
__device__ __forceinline__ uint32_t pack2h(float v0, float v1) {
    __half2 h = __floats2half2_rn(v0, v1);
    return *(uint32_t*)&h;
}

// ---------------- HMMA fp16 GEMM (4-stage, 1 sync/chunk, 2 CTAs/SM) ----------------
// EPI 0: fp16 raw   1: fp32 a*acc+bias+extra
// 4: fp16 silu(a*acc+bias)   5: fp16 (a*acc+bias)*gateh (extra stride = Cp)
#define TILEB 10240
#define STAGE_B 20480
#define GEMM_SMEM (4 * STAGE_B)

template <int EPI>
__device__ __forceinline__ void gemm_body(
    const fp16* __restrict__ A, const fp16* __restrict__ B,
    int Kp, int N,
    float* __restrict__ Cf, fp16* __restrict__ Ch, int Cp,
    const float* __restrict__ sp, int sidx,
    const float* __restrict__ bias, const void* __restrict__ extra) {
    extern __shared__ char smem[];
    uint32_t sb = s2u(smem);
    int tid = threadIdx.x;
    int wid = tid >> 5, lane = tid & 31;
    int m0 = blockIdx.y * 128, n0 = blockIdx.x * 128;
    int wm = (wid & 1) * 64, wn = (wid >> 1) * 32;

    const fp16* bases[2] = {A, B};
    int row0s[2] = {m0, n0};

    auto load_chunk = [&](int ck) {
        uint32_t st = sb + (uint32_t)(ck & 3) * STAGE_B;
        #pragma unroll
        for (int op = 0; op < 2; op++) {
            #pragma unroll
            for (int p = 0; p < 2; p++) {
                int idx = tid + p * 256;
                int r = idx >> 2, cg = idx & 3;
                const fp16* g = bases[op] + (size_t)(row0s[op] + r) * Kp + ck * 32 + cg * 8;
                cpa16(st + (uint32_t)op * TILEB + (uint32_t)(r * 80 + cg * 16), g);
            }
        }
        cpa_commit();
    };

    float acc[4][4][4];
    #pragma unroll
    for (int i = 0; i < 4; i++)
        #pragma unroll
        for (int j = 0; j < 4; j++)
            #pragma unroll
            for (int r = 0; r < 4; r++) acc[i][j][r] = 0.0f;

    const int T = Kp >> 5;
    load_chunk(0);
    load_chunk(1);
    load_chunk(2);

    uint32_t a_off = (uint32_t)((lane & 15) * 80 + (lane >> 4) * 16);
    uint32_t b4_off = (uint32_t)((lane & 15) * 80 + (lane >> 4) * 16);

    for (int ck = 0; ck < T; ck++) {
        if (ck + 2 < T) cpa_wait<2>();
        else if (ck + 1 < T) cpa_wait<1>();
        else cpa_wait<0>();
        __syncthreads();
        // stage (ck+3)&3 == (ck-1)&3: all warps finished reading it before this sync
        if (ck + 3 < T) load_chunk(ck + 3);
        uint32_t st = sb + (uint32_t)(ck & 3) * STAGE_B;
        #pragma unroll
        for (int ks = 0; ks < 2; ks++) {
            uint32_t kb = (uint32_t)(ks * 32);
            uint32_t af[4][4], bq[2][4];
            #pragma unroll
            for (int mp = 0; mp < 4; mp++)
                ldmx4(af[mp], st + (uint32_t)((wm + mp * 16) * 80) + a_off + kb);
            #pragma unroll
            for (int g = 0; g < 2; g++)
                ldmx4(bq[g], st + TILEB + (uint32_t)((wn + g * 16) * 80) + b4_off + kb);
            #pragma unroll
            for (int mp = 0; mp < 4; mp++)
                #pragma unroll
                for (int np = 0; np < 4; np++) {
                    uint32_t bb[2] = {bq[np >> 1][np & 1], bq[np >> 1][(np & 1) + 2]};
                    mma16816(acc[mp][np], af[mp], bb);
                }
        }
    }

    float alpha = 1.0f;
    if (EPI != 0) alpha = sp[0] / g_sigma[sidx];
    int rl = lane >> 2, cl2 = (lane & 3) * 2;

    #pragma unroll
    for (int mp = 0; mp < 4; mp++) {
        #pragma unroll
        for (int np = 0; np < 4; np++) {
            #pragma unroll
            for (int half = 0; half < 2; half++) {
                int gm = m0 + wm + mp * 16 + rl + half * 8;
                int gn = n0 + wn + np * 8 + cl2;
                #pragma unroll
                for (int e = 0; e < 2; e++) {
                    int n = gn + e;
                    if (n >= N) continue;
                    float v = acc[mp][np][half * 2 + e];
                    if (EPI != 0) v = fmaf(alpha, v, bias[n]);
                    if (EPI == 1) v += ((const float*)extra)[(size_t)gm * N + n];
                    if (EPI == 4) v = v / (1.0f + __expf(-v));
                    if (EPI == 5) {
                        float g = __half2float(((const fp16*)extra)[(size_t)gm * Cp + n]);
                        v *= g;
                    }
                    if (EPI == 1) {
                        Cf[(size_t)gm * N + n] = v;
                    } else {
                        Ch[(size_t)gm * Cp + n] = __float2half_rn(v);
                    }
                }
            }
        }
    }
}

template <int EPI>
__global__ __launch_bounds__(256, 2)
void gemm_hmma(const fp16* A, const fp16* B,
               int Kp, int N, float* Cf, fp16* Ch, int Cp,
               const float* sp, int sidx, const float* bias, const void* extra) {
    gemm_body<EPI>(A, B, Kp, N, Cf, Ch, Cp, sp, sidx, bias, extra);
}

struct QKVArgs {
    const fp16* b[3];
    fp16* c[3];
};
__global__ __launch_bounds__(256, 2)
void gemm_qkv(const fp16* A, QKVArgs a) {
    int z = blockIdx.z;
    gemm_body<0>(A, a.b[z], DDIM, DDIM, nullptr, a.c[z], DDIM, nullptr, 0, nullptr, nullptr);
}

// ---------------- weight transpose -> fp16 ----------------
struct WCAll {
    const float* W[7];
    fp16* O[7];
};
__constant__ int wc_K[7]  = {1024, 1024, 1024, 1024, 1024, 1024, 2736};
__constant__ int wc_N[7]  = {1024, 1024, 1024, 1024, 2736, 2736, 1024};
__constant__ int wc_Kp[7] = {1024, 1024, 1024, 1024, 1024, 1024, KPADM};
__constant__ int wc_nb[7] = {1024, 1024, 1024, 1024, 2752, 2752, 2752};

__global__ void wconv_sub(WCAll a, int w0) {
    __shared__ float t[32][33];
    int bid = blockIdx.x, wi = w0;
    while (bid >= wc_nb[wi]) { bid -= wc_nb[wi]; wi++; }
    int K = wc_K[wi], N = wc_N[wi], Kp = wc_Kp[wi];
    int tiles_x = (N + 31) >> 5;
    int bx = (bid % tiles_x) * 32, by = (bid / tiles_x) * 32;
    const float* W = a.W[wi];
    fp16* O = a.O[wi];
    int x = threadIdx.x, y = threadIdx.y;
    for (int yy = y; yy < 32; yy += 8) {
        int k = by + yy, n = bx + x;
        t[yy][x] = (k < K && n < N) ? W[(size_t)k * N + n] : 0.0f;
    }
    __syncthreads();
    for (int yy = y; yy < 32; yy += 8) {
        int n = bx + yy, k = by + x;
        if (n < N && k < K)
            O[(size_t)n * Kp + k] = __float2half_rn(t[x][yy]);
    }
}

// ---------------- power iteration ----------------
__global__ void pi_init(int w0, int wcnt) {
    int idx = blockIdx.x * 256 + threadIdx.x;
    if (idx < wcnt * MDIM) {
        int wi = w0 + idx / MDIM, j = idx % MDIM;
        int cols = c_cols[wi];
        float val = (j < cols) ? 1.0f / (sqrtf((float)cols) + EPSF) : 0.0f;
        g_u[wi][j] = val;
    }
    if (idx < wcnt * 16) g_n2[w0 + idx / 16][idx % 16] = 0.0f;
}
__global__ void pi_zero_u(int w0, int wcnt) {
    int idx = blockIdx.x * 256 + threadIdx.x;
    if (idx < wcnt * MDIM) g_u[w0 + idx / MDIM][idx % MDIM] = 0.0f;
}
__global__ void pi_fwd(WP wp, int t, int w0, int totrows) {
    int gw = (blockIdx.x * blockDim.x + threadIdx.x) >> 5;
    int lane = threadIdx.x & 31;
    if (gw >= totrows) return;
    int wi = w0, r = gw;
    while (r >= c_rows[wi]) { r -= c_rows[wi]; wi++; }
    int cols = c_cols[wi];
    float su = 1.0f;
    if (t > 0) su = 1.0f / (sqrtf(g_n2[wi][8 + t - 1]) + EPSF);
    const float* row = wp.p[wi] + (size_t)r * cols;
    const float* u = g_u[wi];
    float a0 = 0.0f, a1 = 0.0f, a2 = 0.0f, a3 = 0.0f;
    for (int c = lane * 4; c < cols; c += 512) {
        {
            float4 kv = *(const float4*)(row + c);
            float4 uv = *(const float4*)(u + c);
            a0 += kv.x * uv.x + kv.y * uv.y + kv.z * uv.z + kv.w * uv.w;
        }
        if (c + 128 < cols) {
            float4 kv = *(const float4*)(row + c + 128);
            float4 uv = *(const float4*)(u + c + 128);
            a1 += kv.x * uv.x + kv.y * uv.y + kv.z * uv.z + kv.w * uv.w;
        }
        if (c + 256 < cols) {
            float4 kv = *(const float4*)(row + c + 256);
            float4 uv = *(const float4*)(u + c + 256);
            a2 += kv.x * uv.x + kv.y * uv.y + kv.z * uv.z + kv.w * uv.w;
        }
        if (c + 384 < cols) {
            float4 kv = *(const float4*)(row + c + 384);
            float4 uv = *(const float4*)(u + c + 384);
            a3 += kv.x * uv.x + kv.y * uv.y + kv.z * uv.z + kv.w * uv.w;
        }
    }
    float acc = (a0 + a1) + (a2 + a3);
    #pragma unroll
    for (int o = 16; o; o >>= 1) acc += __shfl_xor_sync(0xffffffffu, acc, o);
    if (lane == 0) {
        float y = acc * su;
        g_w[wi][r] = y;
        atomicAdd(&g_n2[wi][t], y * y);
    }
}
__global__ void pi_bwd(WP wp, int t, int w0) {
    __shared__ float ws[BWD_CH];
    int bid = blockIdx.x, wi = w0;
    for (;;) { int nb = c_nct[wi] * c_nrc[wi]; if (bid < nb) break; bid -= nb; wi++; }
    int ct = bid % c_nct[wi], rc = bid / c_nct[wi];
    int rows = c_rows[wi], cols = c_cols[wi];
    float sv = 1.0f / (sqrtf(g_n2[wi][t]) + EPSF);
    int i0 = rc * BWD_CH;
    int ilen = min(BWD_CH, rows - i0);
    for (int i = threadIdx.x; i < ilen; i += 256) ws[i] = g_w[wi][i0 + i] * sv;
    __syncthreads();
    int j = ct * 256 + threadIdx.x;
    if (j < cols) {
        const float* base = wp.p[wi] + (size_t)i0 * cols + j;
        float a0 = 0.0f, a1 = 0.0f, a2 = 0.0f, a3 = 0.0f;
        int i = 0;
        for (; i + 8 <= ilen; i += 8) {
            a0 += base[(size_t)(i + 0) * cols] * ws[i + 0];
            a1 += base[(size_t)(i + 1) * cols] * ws[i + 1];
            a2 += base[(size_t)(i + 2) * cols] * ws[i + 2];
            a3 += base[(size_t)(i + 3) * cols] * ws[i + 3];
            a0 += base[(size_t)(i + 4) * cols] * ws[i + 4];
            a1 += base[(size_t)(i + 5) * cols] * ws[i + 5];
            a2 += base[(size_t)(i + 6) * cols] * ws[i + 6];
            a3 += base[(size_t)(i + 7) * cols] * ws[i + 7];
        }
        for (; i < ilen; i++) a0 += base[(size_t)i * cols] * ws[i];
        atomicAdd(&g_u[wi][j], (a0 + a1) + (a2 + a3));
    }
}
__global__ void pi_norm_u(int t, int w0) {
    int wi = w0 + blockIdx.x;
    int cols = c_cols[wi];
    float s = 0.0f;
    for (int j = threadIdx.x; j < cols; j += 256) { float v = g_u[wi][j]; s += v * v; }
    #pragma unroll
    for (int o = 16; o; o >>= 1) s += __shfl_xor_sync(0xffffffffu, s, o);
    __shared__ float red[8];
    if ((threadIdx.x & 31) == 0) red[threadIdx.x >> 5] = s;
    __syncthreads();
    if (threadIdx.x == 0) {
        float tot = 0.0f;
        #pragma unroll
        for (int i = 0; i < 8; i++) tot += red[i];
        g_n2[wi][8 + t] = tot;
    }
}
__global__ void pi_sigma(int w0, int wcnt) {
    int wi = w0 + threadIdx.x;
    if (threadIdx.x < wcnt) {
        float n2 = g_n2[wi][5];
        float s = sqrtf(n2);
        g_sigma[wi] = fmaxf(n2 / (s + EPSF), EPSF);
    }
}

// ---------------- elementwise ----------------
__global__ void rmsnorm_h(const float* __restrict__ x, const float* __restrict__ sc,
                          fp16* __restrict__ o) {
    int row = blockIdx.x;
    const float* xr = x + (size_t)row * DDIM;
    float4 v = *(const float4*)(xr + threadIdx.x * 4);
    float s = v.x * v.x + v.y * v.y + v.z * v.z + v.w * v.w;
    #pragma unroll
    for (int off = 16; off; off >>= 1) s += __shfl_xor_sync(0xffffffffu, s, off);
    __shared__ float red[8];
    if ((threadIdx.x & 31) == 0) red[threadIdx.x >> 5] = s;
    __syncthreads();
    float tot = 0.0f;
    #pragma unroll
    for (int i = 0; i < 8; i++) tot += red[i];
    float r = rsqrtf(tot * (1.0f / (float)DDIM) + EPSF);
    float4 s4 = *(const float4*)(sc + threadIdx.x * 4);
    size_t base = (size_t)row * DDIM + threadIdx.x * 4;
    *(uint32_t*)(o + base) = pack2h(v.x * r * s4.x, v.y * r * s4.y);
    *(uint32_t*)(o + base + 2) = pack2h(v.z * r * s4.z, v.w * r * s4.w);
}

__global__ void qknorm_h(fp16* __restrict__ q, fp16* __restrict__ k,
                         const float* __restrict__ qsc, const float* __restrict__ ksc,
                         const float* __restrict__ sq, const float* __restrict__ sk,
                         const float* __restrict__ bq, const float* __restrict__ bk) {
    int warp = threadIdx.x >> 5, lane = threadIdx.x & 31;
    int gw = blockIdx.x * 8 + warp;
    int n = gw >> 4, h = gw & 15;
    fp16* p = blockIdx.y ? k : q;
    const float* sc = blockIdx.y ? ksc : qsc;
    const float* bb = blockIdx.y ? bk : bq;
    float alpha = (blockIdx.y ? sk[0] / g_sigma[1] : sq[0] / g_sigma[0]);
    size_t off = (size_t)n * DDIM + h * HDIM + lane * 2;
    __half2 hv = *(__half2*)(p + off);
    float v0 = fmaf(alpha, __half2float(hv.x), bb[h * HDIM + lane * 2]);
    float v1 = fmaf(alpha, __half2float(hv.y), bb[h * HDIM + lane * 2 + 1]);
    float s = v0 * v0 + v1 * v1;
    #pragma unroll
    for (int o = 16; o; o >>= 1) s += __shfl_xor_sync(0xffffffffu, s, o);
    float r = rsqrtf(s * (1.0f / (float)HDIM) + EPSF);
    *(uint32_t*)(p + off) = pack2h(v0 * r * sc[lane * 2], v1 * r * sc[lane * 2 + 1]);
}

// ---------------- HMMA fp16 flash attention (4-stage KV, 1 sync/kt) ----------------
#define ATSB 144
#define KVT 9216
#define ATT_STAGE (2 * KVT)
#define ATT_SMEM (4 * ATT_STAGE)

__global__ __launch_bounds__(256, 2)
void attn_hmma(const fp16* __restrict__ q,
               const fp16* __restrict__ k, const fp16* __restrict__ v,
               fp16* __restrict__ o,
               const float* __restrict__ svp, const float* __restrict__ bv) {
    extern __shared__ char smem[];
    uint32_t sb = s2u(smem);
    int tid = threadIdx.x, wid = tid >> 5, lane = tid & 31;
    int bh = blockIdx.y, b = bh >> 4, h = bh & 15;
    int q0 = blockIdx.x * 128;
    size_t base = ((size_t)b * SEQ) * DDIM + (size_t)h * HDIM;
    int wm = wid * 16;

    // stage Q into stages 0-1 region, extract frags, then release
    #pragma unroll
    for (int p = 0; p < 4; p++) {
        int idx = tid + p * 256;
        int r = idx >> 3, c = idx & 7;
        size_t g = base + (size_t)(q0 + r) * DDIM + c * 8;
        cpa16(sb + (uint32_t)(r * ATSB + c * 16), q + g);
    }
    cpa_commit();
    cpa_wait<0>();
    __syncthreads();
    uint32_t qf[4][4];
    #pragma unroll
    for (int ks = 0; ks < 4; ks++) {
        uint32_t qa = sb + (uint32_t)((wm + (lane & 15)) * ATSB + ks * 32 + (lane >> 4) * 16);
        ldmx4(qf[ks], qa);
    }
    __syncthreads();

    auto load_kv = [&](int kt) {
        uint32_t st = sb + (uint32_t)(kt & 3) * ATT_STAGE;
        int t0 = kt * 64;
        #pragma unroll
        for (int p = 0; p < 2; p++) {
            int idx = tid + p * 256;
            int r = idx >> 3, c = idx & 7;
            size_t g = base + (size_t)(t0 + r) * DDIM + c * 8;
            uint32_t off = (uint32_t)(r * ATSB + c * 16);
            cpa16(st + off, k + g);
            cpa16(st + KVT + off, v + g);
        }
        cpa_commit();
    };
    load_kv(0);
    load_kv(1);
    load_kv(2);

    float O[8][4];
    #pragma unroll
    for (int i = 0; i < 8; i++)
        #pragma unroll
        for (int j = 0; j < 4; j++) O[i][j] = 0.0f;
    float m0v = -1e30f, m1v = -1e30f, l0 = 0.0f, l1 = 0.0f;

    for (int kt = 0; kt < 16; kt++) {
        if (kt + 2 < 16) cpa_wait<2>();
        else if (kt + 1 < 16) cpa_wait<1>();
        else cpa_wait<0>();
        __syncthreads();
        if (kt + 3 < 16) load_kv(kt + 3);   // writes stage (kt-1)&3, safe post-sync
        uint32_t sK = sb + (uint32_t)(kt & 3) * ATT_STAGE;
        uint32_t sV = sK + KVT;

        float S[8][4];
        #pragma unroll
        for (int i = 0; i < 8; i++)
            #pragma unroll
            for (int j = 0; j < 4; j++) S[i][j] = 0.0f;

        #pragma unroll
        for (int ks = 0; ks < 4; ks++) {
            uint32_t kq[4][4];
            #pragma unroll
            for (int nt2 = 0; nt2 < 4; nt2++)
                ldmx4(kq[nt2], sK + (uint32_t)((nt2 * 16 + (lane & 15)) * ATSB + ks * 32 + (lane >> 4) * 16));
            #pragma unroll
            for (int nt = 0; nt < 8; nt++) {
                uint32_t bb[2] = {kq[nt >> 1][nt & 1], kq[nt >> 1][(nt & 1) + 2]};
                mma16816(S[nt], qf[ks], bb);
            }
        }

        #pragma unroll
        for (int nt = 0; nt < 8; nt++)
            #pragma unroll
            for (int j = 0; j < 4; j++) {
                float e = __expf(S[nt][j] * 0.005f);
                S[nt][j] = 50.0f * __fdividef(e - 1.0f, e + 1.0f);
            }

        float mx0 = -1e30f, mx1 = -1e30f;
        #pragma unroll
        for (int nt = 0; nt < 8; nt++) {
            mx0 = fmaxf(mx0, fmaxf(S[nt][0], S[nt][1]));
            mx1 = fmaxf(mx1, fmaxf(S[nt][2], S[nt][3]));
        }
        mx0 = fmaxf(mx0, __shfl_xor_sync(0xffffffffu, mx0, 1));
        mx0 = fmaxf(mx0, __shfl_xor_sync(0xffffffffu, mx0, 2));
        mx1 = fmaxf(mx1, __shfl_xor_sync(0xffffffffu, mx1, 1));
        mx1 = fmaxf(mx1, __shfl_xor_sync(0xffffffffu, mx1, 2));
        float mn0 = fmaxf(m0v, mx0), mn1 = fmaxf(m1v, mx1);
        float c0 = __expf(m0v - mn0), c1 = __expf(m1v - mn1);
        m0v = mn0; m1v = mn1;
        float s0 = 0.0f, s1 = 0.0f;
        #pragma unroll
        for (int nt = 0; nt < 8; nt++) {
            S[nt][0] = __expf(S[nt][0] - mn0);
            S[nt][1] = __expf(S[nt][1] - mn0);
            S[nt][2] = __expf(S[nt][2] - mn1);
            S[nt][3] = __expf(S[nt][3] - mn1);
            s0 += S[nt][0] + S[nt][1];
            s1 += S[nt][2] + S[nt][3];
        }
        s0 += __shfl_xor_sync(0xffffffffu, s0, 1);
        s0 += __shfl_xor_sync(0xffffffffu, s0, 2);
        s1 += __shfl_xor_sync(0xffffffffu, s1, 1);
        s1 += __shfl_xor_sync(0xffffffffu, s1, 2);
        l0 = l0 * c0 + s0;
        l1 = l1 * c1 + s1;
        #pragma unroll
        for (int dt = 0; dt < 8; dt++) {
            O[dt][0] *= c0; O[dt][1] *= c0;
            O[dt][2] *= c1; O[dt][3] *= c1;
        }

        #pragma unroll
        for (int ks2 = 0; ks2 < 4; ks2++) {
            uint32_t pf[4];
            pf[0] = pack2h(S[2 * ks2][0], S[2 * ks2][1]);
            pf[1] = pack2h(S[2 * ks2][2], S[2 * ks2][3]);
            pf[2] = pack2h(S[2 * ks2 + 1][0], S[2 * ks2 + 1][1]);
            pf[3] = pack2h(S[2 * ks2 + 1][2], S[2 * ks2 + 1][3]);
            uint32_t vq[4][4];
            #pragma unroll
            for (int dt2 = 0; dt2 < 4; dt2++)
                ldmx4t(vq[dt2], sV + (uint32_t)((ks2 * 16 + (lane & 15)) * ATSB + dt2 * 32 + (lane >> 4) * 16));
            #pragma unroll
            for (int dt = 0; dt < 8; dt++) {
                uint32_t bb[2] = {vq[dt >> 1][(dt & 1) * 2], vq[dt >> 1][(dt & 1) * 2 + 1]};
                mma16816(O[dt], pf, bb);
            }
        }
    }

    float av = svp[0] / g_sigma[2];
    float i0 = av / l0, i1 = av / l1;
    int r = lane >> 2, c2 = (lane & 3) * 2;
    #pragma unroll
    for (int dt = 0; dt < 8; dt++) {
        #pragma unroll
        for (int half = 0; half < 2; half++) {
            int tok = q0 + wm + r + half * 8;
            float inv = half ? i1 : i0;
            int d = dt * 8 + c2;
            float v0 = fmaf(O[dt][half * 2 + 0], inv, bv[h * HDIM + d]);
            float v1 = fmaf(O[dt][half * 2 + 1], inv, bv[h * HDIM + d + 1]);
            *(uint32_t*)(o + base + (size_t)tok * DDIM + d) = pack2h(v0, v1);
        }
    }
}

// ---------------- host ----------------
static void pi_chain(cudaStream_t s, WP wp, int w0, int wcnt, int totrows,
                     int fwd_blocks, int bwd_blocks) {
    int initb = (wcnt * MDIM + 255) / 256;
    pi_init<<<initb, 256, 0, s>>>(w0, wcnt);
    for (int t = 0; t < 5; t++) {
        pi_fwd<<<fwd_blocks, 256, 0, s>>>(wp, t, w0, totrows);
        pi_zero_u<<<initb, 256, 0, s>>>(w0, wcnt);
        pi_bwd<<<bwd_blocks, 256, 0, s>>>(wp, t, w0);
        pi_norm_u<<<wcnt, 256, 0, s>>>(t, w0);
    }
    pi_fwd<<<fwd_blocks, 256, 0, s>>>(wp, 5, w0, totrows);
    pi_sigma<<<1, 32, 0, s>>>(w0, wcnt);
}

extern "C" void kernel_launch(void* const* d_in, const int* in_sizes, int n_in,
                              void* d_out, int out_size) {
    const float* x   = (const float*)d_in[0];
    const float* ln1 = (const float*)d_in[1];
    const float* wq  = (const float*)d_in[2];
    const float* sq  = (const float*)d_in[3];
    const float* bq  = (const float*)d_in[4];
    const float* wk  = (const float*)d_in[5];
    const float* sk  = (const float*)d_in[6];
    const float* bk  = (const float*)d_in[7];
    const float* wv  = (const float*)d_in[8];
    const float* sv  = (const float*)d_in[9];
    const float* bv  = (const float*)d_in[10];
    const float* qn  = (const float*)d_in[11];
    const float* kn  = (const float*)d_in[12];
    const float* wo  = (const float*)d_in[13];
    const float* so  = (const float*)d_in[14];
    const float* bo  = (const float*)d_in[15];
    const float* ln2 = (const float*)d_in[16];
    const float* wg  = (const float*)d_in[17];
    const float* sg  = (const float*)d_in[18];
    const float* bg  = (const float*)d_in[19];
    const float* wu  = (const float*)d_in[20];
    const float* su  = (const float*)d_in[21];
    const float* bu  = (const float*)d_in[22];
    const float* wd  = (const float*)d_in[23];
    const float* sd  = (const float*)d_in[24];
    const float* bd  = (const float*)d_in[25];
    float* out = (float*)d_out;

    float* p_x1;
    cudaGetSymbolAddress((void**)&p_x1, g_x1);
    fp16* p_gateh;
    cudaGetSymbolAddress((void**)&p_gateh, g_gateh);

    fp16 *ai, *aop, *mi, *hb, *qp, *kp, *vp;
    cudaGetSymbolAddress((void**)&ai, g_ai);
    cudaGetSymbolAddress((void**)&aop, g_aop);
    cudaGetSymbolAddress((void**)&mi, g_mi);
    cudaGetSymbolAddress((void**)&hb, g_hb);
    cudaGetSymbolAddress((void**)&qp, g_q);
    cudaGetSymbolAddress((void**)&kp, g_k);
    cudaGetSymbolAddress((void**)&vp, g_v);

    fp16 *wqT, *wkT, *wvT, *woT, *wgT, *wuT, *wdT;
    cudaGetSymbolAddress((void**)&wqT, g_wqT);
    cudaGetSymbolAddress((void**)&wkT, g_wkT);
    cudaGetSymbolAddress((void**)&wvT, g_wvT);
    cudaGetSymbolAddress((void**)&woT, g_woT);
    cudaGetSymbolAddress((void**)&wgT, g_wgT);
    cudaGetSymbolAddress((void**)&wuT, g_wuT);
    cudaGetSymbolAddress((void**)&wdT, g_wdT);

    cudaFuncSetAttribute(gemm_hmma<1>, cudaFuncAttributeMaxDynamicSharedMemorySize, GEMM_SMEM);
    cudaFuncSetAttribute(gemm_hmma<4>, cudaFuncAttributeMaxDynamicSharedMemorySize, GEMM_SMEM);
    cudaFuncSetAttribute(gemm_hmma<5>, cudaFuncAttributeMaxDynamicSharedMemorySize, GEMM_SMEM);
    cudaFuncSetAttribute(gemm_qkv, cudaFuncAttributeMaxDynamicSharedMemorySize, GEMM_SMEM);
    cudaFuncSetAttribute(attn_hmma, cudaFuncAttributeMaxDynamicSharedMemorySize, ATT_SMEM);

    static cudaStream_t s2 = nullptr, s3 = nullptr, s4 = nullptr;
    static cudaEvent_t evFork = nullptr, evA = nullptr, evO = nullptr,
                       evG = nullptr, evU = nullptr, evD = nullptr;
    if (!s2) {
        cudaStreamCreate(&s2);
        cudaStreamCreate(&s3);
        cudaStreamCreate(&s4);
        cudaEventCreateWithFlags(&evFork, cudaEventDisableTiming);
        cudaEventCreateWithFlags(&evA, cudaEventDisableTiming);
        cudaEventCreateWithFlags(&evO, cudaEventDisableTiming);
        cudaEventCreateWithFlags(&evG, cudaEventDisableTiming);
        cudaEventCreateWithFlags(&evU, cudaEventDisableTiming);
        cudaEventCreateWithFlags(&evD, cudaEventDisableTiming);
    }

    WP wp;
    wp.p[0] = wq; wp.p[1] = wk; wp.p[2] = wv; wp.p[3] = wo;
    wp.p[4] = wg; wp.p[5] = wu; wp.p[6] = wd;

    WCAll wc;
    wc.W[0] = wq; wc.O[0] = wqT;
    wc.W[1] = wk; wc.O[1] = wkT;
    wc.W[2] = wv; wc.O[2] = wvT;
    wc.W[3] = wo; wc.O[3] = woT;
    wc.W[4] = wg; wc.O[4] = wgT;
    wc.W[5] = wu; wc.O[5] = wuT;
    wc.W[6] = wd; wc.O[6] = wdT;

    cudaEventRecord(evFork, 0);
    cudaStreamWaitEvent(s2, evFork, 0);
    cudaStreamWaitEvent(s3, evFork, 0);
    cudaStreamWaitEvent(s4, evFork, 0);

    // s2: PI{qkv} -> evA, then PI{wo} -> evO
    pi_chain(s2, wp, 0, 3, 3072, 384, 3 * 4 * 32);
    cudaEventRecord(evA, s2);
    pi_chain(s2, wp, 3, 1, 1024, 128, 4 * 32);
    cudaEventRecord(evO, s2);

    // s3: wconv{rest}, then PI{wg} -> evG, then PI{wu} -> evU
    wconv_sub<<<9280, dim3(32, 8), 0, s3>>>(wc, 3);
    pi_chain(s3, wp, 4, 1, 1024, 128, 11 * 32);
    cudaEventRecord(evG, s3);
    pi_chain(s3, wp, 5, 1, 1024, 128, 11 * 32);
    cudaEventRecord(evU, s3);

    // s4: PI{wd} -> evD
    pi_chain(s4, wp, 6, 1, 2736, 342, 4 * 86);
    cudaEventRecord(evD, s4);

    // ---- main stream ----
    wconv_sub<<<3072, dim3(32, 8)>>>(wc, 0);
    rmsnorm_h<<<NTOK, 256>>>(x, ln1, ai);

    QKVArgs qa;
    qa.b[0] = wqT; qa.c[0] = qp;
    qa.b[1] = wkT; qa.c[1] = kp;
    qa.b[2] = wvT; qa.c[2] = vp;
    gemm_qkv<<<dim3(8, 32, 3), 256, GEMM_SMEM>>>(ai, qa);

    cudaStreamWaitEvent(0, evA, 0);
    qknorm_h<<<dim3(8192, 2), 256>>>(qp, kp, qn, kn, sq, sk, bq, bk);

    attn_hmma<<<dim3(8, 64), 256, ATT_SMEM>>>(qp, kp, vp, aop, sv, bv);

    cudaStreamWaitEvent(0, evO, 0);
    cudaStreamWaitEvent(0, evG, 0);   // also covers s3's wconv of woT

    dim3 g1(8, 32);
    gemm_hmma<1><<<g1, 256, GEMM_SMEM>>>(aop, woT, 1024, 1024,
                                         p_x1, nullptr, 0, so, 3, bo, x);

    rmsnorm_h<<<NTOK, 256>>>(p_x1, ln2, mi);

    dim3 g2(22, 32);
    gemm_hmma<4><<<g2, 256, GEMM_SMEM>>>(mi, wgT, 1024, 2736,
                                         nullptr, p_gateh, KPADM, sg, 4, bg, nullptr);
    cudaStreamWaitEvent(0, evU, 0);
    gemm_hmma<5><<<g2, 256, GEMM_SMEM>>>(mi, wuT, 1024, 2736,
                                         nullptr, hb, KPADM, su, 5, bu, p_gateh);
    cudaStreamWaitEvent(0, evD, 0);
    gemm_hmma<1><<<g1, 256, GEMM_SMEM>>>(hb, wdT, KPADM, 1024,
                                         out, nullptr, 0, sd, 6, bd, p_x1);
}

// round 17
// speedup vs baseline: 1.0888x; 1.0888x over previous
#include <cuda_runtime.h>
#include <cuda_fp16.h>
#include <math.h>
#include <stdint.h>

#define EPSF 1e-6f
#define NTOK 4096
#define DDIM 1024
#define HDIM 64
#define MDIM 2736
#define SEQ  1024
#define KPADM 2752
#define NPADM 2816

typedef __half fp16;

// ---------------- scratch ----------------
__device__ float g_x1[NTOK * DDIM];
__device__ float g_gate[NTOK * MDIM];

__device__ fp16 g_ai[NTOK * DDIM];
__device__ fp16 g_q[NTOK * DDIM];
__device__ fp16 g_k[NTOK * DDIM];
__device__ fp16 g_v[NTOK * DDIM];
__device__ fp16 g_aop[NTOK * DDIM];
__device__ fp16 g_mi[NTOK * DDIM];
__device__ fp16 g_hb[NTOK * KPADM];

__device__ fp16 g_wqT[DDIM * DDIM];
__device__ fp16 g_wkT[DDIM * DDIM];
__device__ fp16 g_wvT[DDIM * DDIM];
__device__ fp16 g_woT[DDIM * DDIM];
__device__ fp16 g_wgT[NPADM * DDIM];
__device__ fp16 g_wuT[NPADM * DDIM];
__device__ fp16 g_wdT[DDIM * KPADM];

__device__ float g_u[7][MDIM];
__device__ float g_w[7][MDIM];
__device__ float g_n2[7][16];
__device__ float g_sigma[7];

__constant__ int c_rows[7] = {1024, 1024, 1024, 1024, 1024, 1024, 2736};
__constant__ int c_cols[7] = {1024, 1024, 1024, 1024, 2736, 2736, 1024};
__constant__ int c_nct[7]  = {4, 4, 4, 4, 11, 11, 4};
__constant__ int c_nrc[7]  = {8, 8, 8, 8, 8, 8, 22};
#define BWD_CH 128

struct WP { const float* p[7]; };

// ---------------- PTX helpers ----------------
__device__ __forceinline__ uint32_t s2u(const void* p) {
    uint32_t a;
    asm("{ .reg .u64 t; cvta.to.shared.u64 t, %1; cvt.u32.u64 %0, t; }" : "=r"(a) : "l"(p));
    return a;
}
__device__ __forceinline__ void cpa16(uint32_t d, const void* g) {
    asm volatile("cp.async.cg.shared.global [%0], [%1], 16;" :: "r"(d), "l"(g) : "memory");
}
__device__ __forceinline__ void cpa_commit() { asm volatile("cp.async.commit_group;" ::: "memory"); }
template <int N> __device__ __forceinline__ void cpa_wait() {
    asm volatile("cp.async.wait_group %0;" :: "n"(N) : "memory");
}
__device__ __forceinline__ void ldmx4(uint32_t* r, uint32_t a) {
    asm volatile("ldmatrix.sync.aligned.m8n8.x4.shared.b16 {%0,%1,%2,%3}, [%4];"
                 : "=r"(r[0]), "=r"(r[1]), "=r"(r[2]), "=r"(r[3]) : "r"(a));
}
__device__ __forceinline__ void ldmx2(uint32_t* r, uint32_t a) {
    asm volatile("ldmatrix.sync.aligned.m8n8.x2.shared.b16 {%0,%1}, [%2];"
                 : "=r"(r[0]), "=r"(r[1]) : "r"(a));
}
__device__ __forceinline__ void ldmx2t(uint32_t* r, uint32_t a) {
    asm volatile("ldmatrix.sync.aligned.m8n8.x2.trans.shared.b16 {%0,%1}, [%2];"
                 : "=r"(r[0]), "=r"(r[1]) : "r"(a));
}
__device__ __forceinline__ void mma16816(float* c, const uint32_t* a, const uint32_t* b) {
    asm volatile(
        "mma.sync.aligned.m16n8k16.row.col.f32.f16.f16.f32 "
        "{%0,%1,%2,%3}, {%4,%5,%6,%7}, {%8,%9}, {%0,%1,%2,%3};"
        : "+f"(c[0]), "+f"(c[1]), "+f"(c[2]), "+f"(c[3])
        : "r"(a[0]), "r"(a[1]), "r"(a[2]), "r"(a[3]), "r"(b[0]), "r"(b[1]));
}
__device__ __forceinline__ uint32_t pack2h(float v0, float v1) {
    __half2 h = __floats2half2_rn(v0, v1);
    return *(uint32_t*)&h;
}

// ---------------- HMMA fp16 GEMM (3-stage, 2 CTAs/SM) ----------------
// EPI 0: fp16 raw out   1: fp32 alpha*acc+bias+extra   2: fp16 (alpha*acc+bias)*silu(extra)
// 3: fp32 alpha*acc+bias
#define TILEB 10240
#define STAGE_B 20480
#define GEMM_SMEM (3 * STAGE_B)

template <int EPI>
__device__ __forceinline__ void gemm_body(
    const fp16* __restrict__ A, const fp16* __restrict__ B,
    int Kp, int N,
    float* __restrict__ Cf, fp16* __restrict__ Ch, int Cp,
    const float* __restrict__ sp, int sidx,
    const float* __restrict__ bias, const float* __restrict__ extra) {
    extern __shared__ char smem[];
    uint32_t sb = s2u(smem);
    int tid = threadIdx.x;
    int wid = tid >> 5, lane = tid & 31;
    int m0 = blockIdx.y * 128, n0 = blockIdx.x * 128;
    int wm = (wid & 1) * 64, wn = (wid >> 1) * 32;

    const fp16* bases[2] = {A, B};
    int row0s[2] = {m0, n0};

    auto load_chunk = [&](int ck) {
        uint32_t st = sb + (uint32_t)(ck % 3) * STAGE_B;
        #pragma unroll
        for (int op = 0; op < 2; op++) {
            #pragma unroll
            for (int p = 0; p < 2; p++) {
                int idx = tid + p * 256;
                int r = idx >> 2, cg = idx & 3;
                const fp16* g = bases[op] + (size_t)(row0s[op] + r) * Kp + ck * 32 + cg * 8;
                cpa16(st + (uint32_t)op * TILEB + (uint32_t)(r * 80 + cg * 16), g);
            }
        }
        cpa_commit();
    };

    float acc[4][4][4];
    #pragma unroll
    for (int i = 0; i < 4; i++)
        #pragma unroll
        for (int j = 0; j < 4; j++)
            #pragma unroll
            for (int r = 0; r < 4; r++) acc[i][j][r] = 0.0f;

    const int T = Kp >> 5;
    load_chunk(0);
    load_chunk(1);
    load_chunk(2);

    uint32_t a_off = (uint32_t)((lane & 15) * 80 + (lane >> 4) * 16);
    uint32_t b_off = (uint32_t)((lane & 7) * 80 + ((lane >> 3) & 1) * 16);

    for (int ck = 0; ck < T; ck++) {
        if (ck + 2 < T) cpa_wait<2>();
        else if (ck + 1 < T) cpa_wait<1>();
        else cpa_wait<0>();
        __syncthreads();
        uint32_t st = sb + (uint32_t)(ck % 3) * STAGE_B;
        #pragma unroll
        for (int ks = 0; ks < 2; ks++) {
            uint32_t kb = (uint32_t)(ks * 32);
            uint32_t af[4][4], bf[4][2];
            #pragma unroll
            for (int mp = 0; mp < 4; mp++)
                ldmx4(af[mp], st + (uint32_t)((wm + mp * 16) * 80) + a_off + kb);
            #pragma unroll
            for (int np = 0; np < 4; np++)
                ldmx2(bf[np], st + TILEB + (uint32_t)((wn + np * 8) * 80) + b_off + kb);
            #pragma unroll
            for (int mp = 0; mp < 4; mp++)
                #pragma unroll
                for (int np = 0; np < 4; np++)
                    mma16816(acc[mp][np], af[mp], bf[np]);
        }
        __syncthreads();
        if (ck + 3 < T) load_chunk(ck + 3);
    }

    float alpha = 1.0f;
    if (EPI != 0) alpha = sp[0] / g_sigma[sidx];
    int rl = lane >> 2, cl2 = (lane & 3) * 2;

    #pragma unroll
    for (int mp = 0; mp < 4; mp++) {
        #pragma unroll
        for (int np = 0; np < 4; np++) {
            #pragma unroll
            for (int half = 0; half < 2; half++) {
                int gm = m0 + wm + mp * 16 + rl + half * 8;
                int gn = n0 + wn + np * 8 + cl2;
                #pragma unroll
                for (int e = 0; e < 2; e++) {
                    int n = gn + e;
                    if (n >= N) continue;
                    float v = acc[mp][np][half * 2 + e];
                    if (EPI != 0) v = fmaf(alpha, v, bias[n]);
                    if (EPI == 1) v += extra[(size_t)gm * N + n];
                    if (EPI == 2) {
                        float g = extra[(size_t)gm * N + n];
                        v = v * (g / (1.0f + __expf(-g)));
                    }
                    if (EPI == 0 || EPI == 2) {
                        Ch[(size_t)gm * Cp + n] = __float2half_rn(v);
                    } else {
                        Cf[(size_t)gm * N + n] = v;
                    }
                }
            }
        }
    }
}

template <int EPI>
__global__ __launch_bounds__(256, 2)
void gemm_hmma(const fp16* A, const fp16* B,
               int Kp, int N, float* Cf, fp16* Ch, int Cp,
               const float* sp, int sidx, const float* bias, const float* extra) {
    gemm_body<EPI>(A, B, Kp, N, Cf, Ch, Cp, sp, sidx, bias, extra);
}

struct QKVArgs {
    const fp16* b[3];
    fp16* c[3];
};
__global__ __launch_bounds__(256, 2)
void gemm_qkv(const fp16* A, QKVArgs a) {
    int z = blockIdx.z;
    gemm_body<0>(A, a.b[z], DDIM, DDIM, nullptr, a.c[z], DDIM, nullptr, 0, nullptr, nullptr);
}

// ---------------- weight transpose -> fp16 ----------------
struct WCAll {
    const float* W[7];
    fp16* O[7];
};
__constant__ int wc_K[7]  = {1024, 1024, 1024, 1024, 1024, 1024, 2736};
__constant__ int wc_N[7]  = {1024, 1024, 1024, 1024, 2736, 2736, 1024};
__constant__ int wc_Kp[7] = {1024, 1024, 1024, 1024, 1024, 1024, KPADM};
__constant__ int wc_nb[7] = {1024, 1024, 1024, 1024, 2752, 2752, 2752};

__global__ void wconv_sub(WCAll a, int w0) {
    __shared__ float t[32][33];
    int bid = blockIdx.x, wi = w0;
    while (bid >= wc_nb[wi]) { bid -= wc_nb[wi]; wi++; }
    int K = wc_K[wi], N = wc_N[wi], Kp = wc_Kp[wi];
    int tiles_x = (N + 31) >> 5;
    int bx = (bid % tiles_x) * 32, by = (bid / tiles_x) * 32;
    const float* W = a.W[wi];
    fp16* O = a.O[wi];
    int x = threadIdx.x, y = threadIdx.y;
    for (int yy = y; yy < 32; yy += 8) {
        int k = by + yy, n = bx + x;
        t[yy][x] = (k < K && n < N) ? W[(size_t)k * N + n] : 0.0f;
    }
    __syncthreads();
    for (int yy = y; yy < 32; yy += 8) {
        int n = bx + yy, k = by + x;
        if (n < N && k < K)
            O[(size_t)n * Kp + k] = __float2half_rn(t[x][yy]);
    }
}

// ---------------- power iteration ----------------
__global__ void pi_init(int w0, int wcnt) {
    int idx = blockIdx.x * 256 + threadIdx.x;
    if (idx < wcnt * MDIM) {
        int wi = w0 + idx / MDIM, j = idx % MDIM;
        int cols = c_cols[wi];
        float val = (j < cols) ? 1.0f / (sqrtf((float)cols) + EPSF) : 0.0f;
        g_u[wi][j] = val;
    }
    if (idx < wcnt * 16) g_n2[w0 + idx / 16][idx % 16] = 0.0f;
}
__global__ void pi_zero_u(int w0, int wcnt) {
    int idx = blockIdx.x * 256 + threadIdx.x;
    if (idx < wcnt * MDIM) g_u[w0 + idx / MDIM][idx % MDIM] = 0.0f;
}
__global__ void pi_fwd(WP wp, int t, int w0, int totrows) {
    int gw = (blockIdx.x * blockDim.x + threadIdx.x) >> 5;
    int lane = threadIdx.x & 31;
    if (gw >= totrows) return;
    int wi = w0, r = gw;
    while (r >= c_rows[wi]) { r -= c_rows[wi]; wi++; }
    int cols = c_cols[wi];
    float su = 1.0f;
    if (t > 0) su = 1.0f / (sqrtf(g_n2[wi][8 + t - 1]) + EPSF);
    const float* row = wp.p[wi] + (size_t)r * cols;
    const float* u = g_u[wi];
    float a0 = 0.0f, a1 = 0.0f, a2 = 0.0f, a3 = 0.0f;
    for (int c = lane * 4; c < cols; c += 512) {
        {
            float4 kv = *(const float4*)(row + c);
            float4 uv = *(const float4*)(u + c);
            a0 += kv.x * uv.x + kv.y * uv.y + kv.z * uv.z + kv.w * uv.w;
        }
        if (c + 128 < cols) {
            float4 kv = *(const float4*)(row + c + 128);
            float4 uv = *(const float4*)(u + c + 128);
            a1 += kv.x * uv.x + kv.y * uv.y + kv.z * uv.z + kv.w * uv.w;
        }
        if (c + 256 < cols) {
            float4 kv = *(const float4*)(row + c + 256);
            float4 uv = *(const float4*)(u + c + 256);
            a2 += kv.x * uv.x + kv.y * uv.y + kv.z * uv.z + kv.w * uv.w;
        }
        if (c + 384 < cols) {
            float4 kv = *(const float4*)(row + c + 384);
            float4 uv = *(const float4*)(u + c + 384);
            a3 += kv.x * uv.x + kv.y * uv.y + kv.z * uv.z + kv.w * uv.w;
        }
    }
    float acc = (a0 + a1) + (a2 + a3);
    #pragma unroll
    for (int o = 16; o; o >>= 1) acc += __shfl_xor_sync(0xffffffffu, acc, o);
    if (lane == 0) {
        float y = acc * su;
        g_w[wi][r] = y;
        atomicAdd(&g_n2[wi][t], y * y);
    }
}
__global__ void pi_bwd(WP wp, int t, int w0) {
    __shared__ float ws[BWD_CH];
    int bid = blockIdx.x, wi = w0;
    for (;;) { int nb = c_nct[wi] * c_nrc[wi]; if (bid < nb) break; bid -= nb; wi++; }
    int ct = bid % c_nct[wi], rc = bid / c_nct[wi];
    int rows = c_rows[wi], cols = c_cols[wi];
    float sv = 1.0f / (sqrtf(g_n2[wi][t]) + EPSF);
    int i0 = rc * BWD_CH;
    int ilen = min(BWD_CH, rows - i0);
    for (int i = threadIdx.x; i < ilen; i += 256) ws[i] = g_w[wi][i0 + i] * sv;
    __syncthreads();
    int j = ct * 256 + threadIdx.x;
    if (j < cols) {
        const float* base = wp.p[wi] + (size_t)i0 * cols + j;
        float a0 = 0.0f, a1 = 0.0f, a2 = 0.0f, a3 = 0.0f;
        int i = 0;
        for (; i + 8 <= ilen; i += 8) {
            a0 += base[(size_t)(i + 0) * cols] * ws[i + 0];
            a1 += base[(size_t)(i + 1) * cols] * ws[i + 1];
            a2 += base[(size_t)(i + 2) * cols] * ws[i + 2];
            a3 += base[(size_t)(i + 3) * cols] * ws[i + 3];
            a0 += base[(size_t)(i + 4) * cols] * ws[i + 4];
            a1 += base[(size_t)(i + 5) * cols] * ws[i + 5];
            a2 += base[(size_t)(i + 6) * cols] * ws[i + 6];
            a3 += base[(size_t)(i + 7) * cols] * ws[i + 7];
        }
        for (; i < ilen; i++) a0 += base[(size_t)i * cols] * ws[i];
        atomicAdd(&g_u[wi][j], (a0 + a1) + (a2 + a3));
    }
}
__global__ void pi_norm_u(int t, int w0) {
    int wi = w0 + blockIdx.x;
    int cols = c_cols[wi];
    float s = 0.0f;
    for (int j = threadIdx.x; j < cols; j += 256) { float v = g_u[wi][j]; s += v * v; }
    #pragma unroll
    for (int o = 16; o; o >>= 1) s += __shfl_xor_sync(0xffffffffu, s, o);
    __shared__ float red[8];
    if ((threadIdx.x & 31) == 0) red[threadIdx.x >> 5] = s;
    __syncthreads();
    if (threadIdx.x == 0) {
        float tot = 0.0f;
        #pragma unroll
        for (int i = 0; i < 8; i++) tot += red[i];
        g_n2[wi][8 + t] = tot;
    }
}
__global__ void pi_sigma(int w0, int wcnt) {
    int wi = w0 + threadIdx.x;
    if (threadIdx.x < wcnt) {
        float n2 = g_n2[wi][5];
        float s = sqrtf(n2);
        g_sigma[wi] = fmaxf(n2 / (s + EPSF), EPSF);
    }
}

// ---------------- elementwise ----------------
__global__ void rmsnorm_h(const float* __restrict__ x, const float* __restrict__ sc,
                          fp16* __restrict__ o) {
    int row = blockIdx.x;
    const float* xr = x + (size_t)row * DDIM;
    float4 v = *(const float4*)(xr + threadIdx.x * 4);
    float s = v.x * v.x + v.y * v.y + v.z * v.z + v.w * v.w;
    #pragma unroll
    for (int off = 16; off; off >>= 1) s += __shfl_xor_sync(0xffffffffu, s, off);
    __shared__ float red[8];
    if ((threadIdx.x & 31) == 0) red[threadIdx.x >> 5] = s;
    __syncthreads();
    float tot = 0.0f;
    #pragma unroll
    for (int i = 0; i < 8; i++) tot += red[i];
    float r = rsqrtf(tot * (1.0f / (float)DDIM) + EPSF);
    float4 s4 = *(const float4*)(sc + threadIdx.x * 4);
    size_t base = (size_t)row * DDIM + threadIdx.x * 4;
    *(uint32_t*)(o + base) = pack2h(v.x * r * s4.x, v.y * r * s4.y);
    *(uint32_t*)(o + base + 2) = pack2h(v.z * r * s4.z, v.w * r * s4.w);
}

__global__ void qknorm_h(fp16* __restrict__ q, fp16* __restrict__ k,
                         const float* __restrict__ qsc, const float* __restrict__ ksc,
                         const float* __restrict__ sq, const float* __restrict__ sk,
                         const float* __restrict__ bq, const float* __restrict__ bk) {
    int warp = threadIdx.x >> 5, lane = threadIdx.x & 31;
    int gw = blockIdx.x * 8 + warp;
    int n = gw >> 4, h = gw & 15;
    fp16* p = blockIdx.y ? k : q;
    const float* sc = blockIdx.y ? ksc : qsc;
    const float* bb = blockIdx.y ? bk : bq;
    float alpha = (blockIdx.y ? sk[0] / g_sigma[1] : sq[0] / g_sigma[0]);
    size_t off = (size_t)n * DDIM + h * HDIM + lane * 2;
    __half2 hv = *(__half2*)(p + off);
    float v0 = fmaf(alpha, __half2float(hv.x), bb[h * HDIM + lane * 2]);
    float v1 = fmaf(alpha, __half2float(hv.y), bb[h * HDIM + lane * 2 + 1]);
    float s = v0 * v0 + v1 * v1;
    #pragma unroll
    for (int o = 16; o; o >>= 1) s += __shfl_xor_sync(0xffffffffu, s, o);
    float r = rsqrtf(s * (1.0f / (float)HDIM) + EPSF);
    *(uint32_t*)(p + off) = pack2h(v0 * r * sc[lane * 2], v1 * r * sc[lane * 2 + 1]);
}

// ---------------- HMMA fp16 flash attention (Q in regs, 2 CTAs/SM) ----------------
#define ATSB 144
#define KVT 9216
#define ATT_STAGE (2 * KVT)
#define ATT_SMEM (2 * ATT_STAGE)

__global__ __launch_bounds__(256, 2)
void attn_hmma(const fp16* __restrict__ q,
               const fp16* __restrict__ k, const fp16* __restrict__ v,
               fp16* __restrict__ o,
               const float* __restrict__ svp, const float* __restrict__ bv) {
    extern __shared__ char smem[];
    uint32_t sb = s2u(smem);
    int tid = threadIdx.x, wid = tid >> 5, lane = tid & 31;
    int bh = blockIdx.y, b = bh >> 4, h = bh & 15;
    int q0 = blockIdx.x * 128;
    size_t base = ((size_t)b * SEQ) * DDIM + (size_t)h * HDIM;
    int wm = wid * 16;

    // stage Q into stage0 region, extract frags
    #pragma unroll
    for (int p = 0; p < 4; p++) {
        int idx = tid + p * 256;
        int r = idx >> 3, c = idx & 7;
        size_t g = base + (size_t)(q0 + r) * DDIM + c * 8;
        cpa16(sb + (uint32_t)(r * ATSB + c * 16), q + g);
    }
    cpa_commit();
    cpa_wait<0>();
    __syncthreads();
    uint32_t qf[4][4];
    #pragma unroll
    for (int ks = 0; ks < 4; ks++) {
        uint32_t qa = sb + (uint32_t)((wm + (lane & 15)) * ATSB + ks * 32 + (lane >> 4) * 16);
        ldmx4(qf[ks], qa);
    }
    __syncthreads();

    auto load_kv = [&](int kt) {
        uint32_t st = sb + (uint32_t)(kt & 1) * ATT_STAGE;
        int t0 = kt * 64;
        #pragma unroll
        for (int p = 0; p < 2; p++) {
            int idx = tid + p * 256;
            int r = idx >> 3, c = idx & 7;
            size_t g = base + (size_t)(t0 + r) * DDIM + c * 8;
            uint32_t off = (uint32_t)(r * ATSB + c * 16);
            cpa16(st + off, k + g);
            cpa16(st + KVT + off, v + g);
        }
        cpa_commit();
    };
    load_kv(0);
    load_kv(1);

    float O[8][4];
    #pragma unroll
    for (int i = 0; i < 8; i++)
        #pragma unroll
        for (int j = 0; j < 4; j++) O[i][j] = 0.0f;
    float m0v = -1e30f, m1v = -1e30f, l0 = 0.0f, l1 = 0.0f;

    for (int kt = 0; kt < 16; kt++) {
        if (kt < 15) cpa_wait<1>(); else cpa_wait<0>();
        __syncthreads();
        uint32_t sK = sb + (uint32_t)(kt & 1) * ATT_STAGE;
        uint32_t sV = sK + KVT;

        float S[8][4];
        #pragma unroll
        for (int i = 0; i < 8; i++)
            #pragma unroll
            for (int j = 0; j < 4; j++) S[i][j] = 0.0f;

        #pragma unroll
        for (int ks = 0; ks < 4; ks++) {
            #pragma unroll
            for (int nt = 0; nt < 8; nt++) {
                uint32_t kf[2];
                uint32_t ka = sK + (uint32_t)((nt * 8 + (lane & 7)) * ATSB + ks * 32 + ((lane >> 3) & 1) * 16);
                ldmx2(kf, ka);
                mma16816(S[nt], qf[ks], kf);
            }
        }

        #pragma unroll
        for (int nt = 0; nt < 8; nt++)
            #pragma unroll
            for (int j = 0; j < 4; j++) {
                float e = __expf(S[nt][j] * 0.005f);
                S[nt][j] = 50.0f * __fdividef(e - 1.0f, e + 1.0f);
            }

        float mx0 = -1e30f, mx1 = -1e30f;
        #pragma unroll
        for (int nt = 0; nt < 8; nt++) {
            mx0 = fmaxf(mx0, fmaxf(S[nt][0], S[nt][1]));
            mx1 = fmaxf(mx1, fmaxf(S[nt][2], S[nt][3]));
        }
        mx0 = fmaxf(mx0, __shfl_xor_sync(0xffffffffu, mx0, 1));
        mx0 = fmaxf(mx0, __shfl_xor_sync(0xffffffffu, mx0, 2));
        mx1 = fmaxf(mx1, __shfl_xor_sync(0xffffffffu, mx1, 1));
        mx1 = fmaxf(mx1, __shfl_xor_sync(0xffffffffu, mx1, 2));
        float mn0 = fmaxf(m0v, mx0), mn1 = fmaxf(m1v, mx1);
        float c0 = __expf(m0v - mn0), c1 = __expf(m1v - mn1);
        m0v = mn0; m1v = mn1;
        float s0 = 0.0f, s1 = 0.0f;
        #pragma unroll
        for (int nt = 0; nt < 8; nt++) {
            S[nt][0] = __expf(S[nt][0] - mn0);
            S[nt][1] = __expf(S[nt][1] - mn0);
            S[nt][2] = __expf(S[nt][2] - mn1);
            S[nt][3] = __expf(S[nt][3] - mn1);
            s0 += S[nt][0] + S[nt][1];
            s1 += S[nt][2] + S[nt][3];
        }
        s0 += __shfl_xor_sync(0xffffffffu, s0, 1);
        s0 += __shfl_xor_sync(0xffffffffu, s0, 2);
        s1 += __shfl_xor_sync(0xffffffffu, s1, 1);
        s1 += __shfl_xor_sync(0xffffffffu, s1, 2);
        l0 = l0 * c0 + s0;
        l1 = l1 * c1 + s1;
        #pragma unroll
        for (int dt = 0; dt < 8; dt++) {
            O[dt][0] *= c0; O[dt][1] *= c0;
            O[dt][2] *= c1; O[dt][3] *= c1;
        }

        #pragma unroll
        for (int ks2 = 0; ks2 < 4; ks2++) {
            uint32_t pf[4];
            pf[0] = pack2h(S[2 * ks2][0], S[2 * ks2][1]);
            pf[1] = pack2h(S[2 * ks2][2], S[2 * ks2][3]);
            pf[2] = pack2h(S[2 * ks2 + 1][0], S[2 * ks2 + 1][1]);
            pf[3] = pack2h(S[2 * ks2 + 1][2], S[2 * ks2 + 1][3]);
            #pragma unroll
            for (int dt = 0; dt < 8; dt++) {
                uint32_t vf[2];
                uint32_t va = sV + (uint32_t)((ks2 * 16 + (lane & 15)) * ATSB + dt * 16);
                ldmx2t(vf, va);
                mma16816(O[dt], pf, vf);
            }
        }
        __syncthreads();
        if (kt + 2 < 16) load_kv(kt + 2);
    }

    float av = svp[0] / g_sigma[2];
    float i0 = av / l0, i1 = av / l1;
    int r = lane >> 2, c2 = (lane & 3) * 2;
    #pragma unroll
    for (int dt = 0; dt < 8; dt++) {
        #pragma unroll
        for (int half = 0; half < 2; half++) {
            int tok = q0 + wm + r + half * 8;
            float inv = half ? i1 : i0;
            int d = dt * 8 + c2;
            float v0 = fmaf(O[dt][half * 2 + 0], inv, bv[h * HDIM + d]);
            float v1 = fmaf(O[dt][half * 2 + 1], inv, bv[h * HDIM + d + 1]);
            *(uint32_t*)(o + base + (size_t)tok * DDIM + d) = pack2h(v0, v1);
        }
    }
}

// ---------------- host ----------------
static void pi_chain(cudaStream_t s, WP wp, int w0, int wcnt, int totrows,
                     int fwd_blocks, int bwd_blocks) {
    int initb = (wcnt * MDIM + 255) / 256;
    pi_init<<<initb, 256, 0, s>>>(w0, wcnt);
    for (int t = 0; t < 5; t++) {
        pi_fwd<<<fwd_blocks, 256, 0, s>>>(wp, t, w0, totrows);
        pi_zero_u<<<initb, 256, 0, s>>>(w0, wcnt);
        pi_bwd<<<bwd_blocks, 256, 0, s>>>(wp, t, w0);
        pi_norm_u<<<wcnt, 256, 0, s>>>(t, w0);
    }
    pi_fwd<<<fwd_blocks, 256, 0, s>>>(wp, 5, w0, totrows);
    pi_sigma<<<1, 32, 0, s>>>(w0, wcnt);
}

extern "C" void kernel_launch(void* const* d_in, const int* in_sizes, int n_in,
                              void* d_out, int out_size) {
    const float* x   = (const float*)d_in[0];
    const float* ln1 = (const float*)d_in[1];
    const float* wq  = (const float*)d_in[2];
    const float* sq  = (const float*)d_in[3];
    const float* bq  = (const float*)d_in[4];
    const float* wk  = (const float*)d_in[5];
    const float* sk  = (const float*)d_in[6];
    const float* bk  = (const float*)d_in[7];
    const float* wv  = (const float*)d_in[8];
    const float* sv  = (const float*)d_in[9];
    const float* bv  = (const float*)d_in[10];
    const float* qn  = (const float*)d_in[11];
    const float* kn  = (const float*)d_in[12];
    const float* wo  = (const float*)d_in[13];
    const float* so  = (const float*)d_in[14];
    const float* bo  = (const float*)d_in[15];
    const float* ln2 = (const float*)d_in[16];
    const float* wg  = (const float*)d_in[17];
    const float* sg  = (const float*)d_in[18];
    const float* bg  = (const float*)d_in[19];
    const float* wu  = (const float*)d_in[20];
    const float* su  = (const float*)d_in[21];
    const float* bu  = (const float*)d_in[22];
    const float* wd  = (const float*)d_in[23];
    const float* sd  = (const float*)d_in[24];
    const float* bd  = (const float*)d_in[25];
    float* out = (float*)d_out;

    float *p_x1, *p_gate;
    cudaGetSymbolAddress((void**)&p_x1, g_x1);
    cudaGetSymbolAddress((void**)&p_gate, g_gate);

    fp16 *ai, *aop, *mi, *hb, *qp, *kp, *vp;
    cudaGetSymbolAddress((void**)&ai, g_ai);
    cudaGetSymbolAddress((void**)&aop, g_aop);
    cudaGetSymbolAddress((void**)&mi, g_mi);
    cudaGetSymbolAddress((void**)&hb, g_hb);
    cudaGetSymbolAddress((void**)&qp, g_q);
    cudaGetSymbolAddress((void**)&kp, g_k);
    cudaGetSymbolAddress((void**)&vp, g_v);

    fp16 *wqT, *wkT, *wvT, *woT, *wgT, *wuT, *wdT;
    cudaGetSymbolAddress((void**)&wqT, g_wqT);
    cudaGetSymbolAddress((void**)&wkT, g_wkT);
    cudaGetSymbolAddress((void**)&wvT, g_wvT);
    cudaGetSymbolAddress((void**)&woT, g_woT);
    cudaGetSymbolAddress((void**)&wgT, g_wgT);
    cudaGetSymbolAddress((void**)&wuT, g_wuT);
    cudaGetSymbolAddress((void**)&wdT, g_wdT);

    cudaFuncSetAttribute(gemm_hmma<1>, cudaFuncAttributeMaxDynamicSharedMemorySize, GEMM_SMEM);
    cudaFuncSetAttribute(gemm_hmma<2>, cudaFuncAttributeMaxDynamicSharedMemorySize, GEMM_SMEM);
    cudaFuncSetAttribute(gemm_hmma<3>, cudaFuncAttributeMaxDynamicSharedMemorySize, GEMM_SMEM);
    cudaFuncSetAttribute(gemm_qkv, cudaFuncAttributeMaxDynamicSharedMemorySize, GEMM_SMEM);
    cudaFuncSetAttribute(attn_hmma, cudaFuncAttributeMaxDynamicSharedMemorySize, ATT_SMEM);

    static cudaStream_t s2 = nullptr, s3 = nullptr;
    static cudaEvent_t evFork = nullptr, evA = nullptr, evB = nullptr;
    if (!s2) {
        cudaStreamCreate(&s2);
        cudaStreamCreate(&s3);
        cudaEventCreateWithFlags(&evFork, cudaEventDisableTiming);
        cudaEventCreateWithFlags(&evA, cudaEventDisableTiming);
        cudaEventCreateWithFlags(&evB, cudaEventDisableTiming);
    }

    WP wp;
    wp.p[0] = wq; wp.p[1] = wk; wp.p[2] = wv; wp.p[3] = wo;
    wp.p[4] = wg; wp.p[5] = wu; wp.p[6] = wd;

    WCAll wc;
    wc.W[0] = wq; wc.O[0] = wqT;
    wc.W[1] = wk; wc.O[1] = wkT;
    wc.W[2] = wv; wc.O[2] = wvT;
    wc.W[3] = wo; wc.O[3] = woT;
    wc.W[4] = wg; wc.O[4] = wgT;
    wc.W[5] = wu; wc.O[5] = wuT;
    wc.W[6] = wd; wc.O[6] = wdT;

    cudaEventRecord(evFork, 0);
    cudaStreamWaitEvent(s2, evFork, 0);
    cudaStreamWaitEvent(s3, evFork, 0);

    // ---- s2: PI over {wq,wk,wv} -> evA (R10 layout) ----
    pi_chain(s2, wp, 0, 3, 3072, 384, 96);
    cudaEventRecord(evA, s2);

    // ---- s3: wconv{rest} + PI over {wo,wg,wu,wd} -> evB (R10 layout) ----
    wconv_sub<<<9280, dim3(32, 8), 0, s3>>>(wc, 3);
    pi_chain(s3, wp, 3, 4, 5808, 726, 296);
    cudaEventRecord(evB, s3);

    // ---- main stream ----
    wconv_sub<<<3072, dim3(32, 8)>>>(wc, 0);
    rmsnorm_h<<<NTOK, 256>>>(x, ln1, ai);

    QKVArgs qa;
    qa.b[0] = wqT; qa.c[0] = qp;
    qa.b[1] = wkT; qa.c[1] = kp;
    qa.b[2] = wvT; qa.c[2] = vp;
    gemm_qkv<<<dim3(8, 32, 3), 256, GEMM_SMEM>>>(ai, qa);

    cudaStreamWaitEvent(0, evA, 0);

    qknorm_h<<<dim3(8192, 2), 256>>>(qp, kp, qn, kn, sq, sk, bq, bk);

    attn_hmma<<<dim3(8, 64), 256, ATT_SMEM>>>(qp, kp, vp, aop, sv, bv);

    cudaStreamWaitEvent(0, evB, 0);

    dim3 g1(8, 32);
    gemm_hmma<1><<<g1, 256, GEMM_SMEM>>>(aop, woT, 1024, 1024,
                                         p_x1, nullptr, 0, so, 3, bo, x);

    rmsnorm_h<<<NTOK, 256>>>(p_x1, ln2, mi);

    dim3 g2(22, 32);
    gemm_hmma<3><<<g2, 256, GEMM_SMEM>>>(mi, wgT, 1024, 2736,
                                         p_gate, nullptr, 0, sg, 4, bg, nullptr);
    gemm_hmma<2><<<g2, 256, GEMM_SMEM>>>(mi, wuT, 1024, 2736,
                                         nullptr, hb, KPADM, su, 5, bu, p_gate);
    gemm_hmma<1><<<g1, 256, GEMM_SMEM>>>(hb, wdT, KPADM, 1024,
                                         out, nullptr, 0, sd, 6, bd, p_x1);
}